// round 6
// baseline (speedup 1.0000x reference)
#include <cuda_runtime.h>

#define SEQ   512
#define BATCH 2048
#define IND   4
#define H     50
#define BT    16                 // batch tile per CTA
#define NCTA  (BATCH / BT)       // 128
#define NTHR  640                // 20 warps, 5 per SMSP exactly
#define HP    56                 // floats per h row: 50 h + 4 x + 2 pad = 28 pairs
#define NPAIR 28

typedef unsigned long long ull;

// ---- packed dual-fp32 (sm_103a FFMA2 path, PTX-only) ----
__device__ __forceinline__ ull pack2(float lo, float hi) {
    ull r; asm("mov.b64 %0, {%1, %2};" : "=l"(r) : "f"(lo), "f"(hi)); return r;
}
__device__ __forceinline__ void unpack2(ull v, float& lo, float& hi) {
    asm("mov.b64 {%0, %1}, %2;" : "=f"(lo), "=f"(hi) : "l"(v));
}
__device__ __forceinline__ void fma2(ull& d, ull a, ull b) {
    asm("fma.rn.f32x2 %0, %1, %2, %0;" : "+l"(d) : "l"(a), "l"(b));
}
__device__ __forceinline__ ull add2(ull a, ull b) {
    ull r; asm("add.rn.f32x2 %0, %1, %2;" : "=l"(r) : "l"(a), "l"(b)); return r;
}

// ---- fast-but-accurate-enough activations (known: final rel_err ~1.5e-7) ----
__device__ __forceinline__ float sigf(float x) {
    return __fdividef(1.0f, 1.0f + __expf(-x));
}
__device__ __forceinline__ float tanh_fast(float x) {
    float ax = fabsf(x);
    float e  = __expf(-2.0f * ax);
    float t  = __fdividef(1.0f - e, 1.0f + e);
    return copysignf(t, x);
}

struct Smem {
    float h1s [BT][HP];      // layer1 h (+ x in slots 50..53, zeros 54..55)
    float h1rs[BT][HP];      // relu(h1)  (slots 50..55 stay zero)
    float h2s [BT][HP];      // layer2 h
    float h2rs[BT][HP];      // relu(h2)
    ull   g1p [200 * BT];    // L1 gate pair-sums
    ull   g2ap[200 * BT];    // L2 w_ih2 part
    ull   g2bp[200 * BT];    // L2 w_hh2 part
    float b1c[200];          // b_ih1 + b_hh1
    float b2c[200];          // b_ih2 + b_hh2
    float xs[BT][IND];       // staged x(t+1)
    float wfcs[52];
    float bfcs;
};

__device__ __forceinline__ float hsum2(ull v, float bias) {
    float lo, hi; unpack2(v, lo, hi);
    return (lo + hi) + bias;
}

__device__ __forceinline__ void l1_update(Smem* S, int u, int b, float& c) {
    float gi = hsum2(S->g1p[(      u) * BT + b], S->b1c[u]);
    float gf = hsum2(S->g1p[(H   + u) * BT + b], S->b1c[H + u]);
    float gg = hsum2(S->g1p[(2*H + u) * BT + b], S->b1c[2*H + u]);
    float go = hsum2(S->g1p[(3*H + u) * BT + b], S->b1c[3*H + u]);
    float cn = sigf(gf) * c + sigf(gi) * tanh_fast(gg);
    c = cn;
    float hv = sigf(go) * tanh_fast(cn);
    S->h1s[b][u]  = hv;
    S->h1rs[b][u] = fmaxf(hv, 0.f);
}

__device__ __forceinline__ void l2_update(Smem* S, int u, int b, float& c) {
    float gi = hsum2(add2(S->g2ap[(      u) * BT + b], S->g2bp[(      u) * BT + b]), S->b2c[u]);
    float gf = hsum2(add2(S->g2ap[(H   + u) * BT + b], S->g2bp[(H   + u) * BT + b]), S->b2c[H + u]);
    float gg = hsum2(add2(S->g2ap[(2*H + u) * BT + b], S->g2bp[(2*H + u) * BT + b]), S->b2c[2*H + u]);
    float go = hsum2(add2(S->g2ap[(3*H + u) * BT + b], S->g2bp[(3*H + u) * BT + b]), S->b2c[3*H + u]);
    float cn = sigf(gf) * c + sigf(gi) * tanh_fast(gg);
    c = cn;
    float hv = sigf(go) * tanh_fast(cn);
    S->h2s[b][u]  = hv;
    S->h2rs[b][u] = fmaxf(hv, 0.f);
}

__global__ __launch_bounds__(NTHR, 1)
void lstm_fused_kernel(
    const float* __restrict__ x,
    const float* __restrict__ w_ih1, const float* __restrict__ w_hh1,
    const float* __restrict__ b_ih1, const float* __restrict__ b_hh1,
    const float* __restrict__ w_ih2, const float* __restrict__ w_hh2,
    const float* __restrict__ b_ih2, const float* __restrict__ b_hh2,
    const float* __restrict__ w_fc,  const float* __restrict__ b_fc,
    float* __restrict__ out)
{
    extern __shared__ char smem_raw[];
    Smem* S = (Smem*)smem_raw;

    const int tid = threadIdx.x;
    const int B0  = blockIdx.x * BT;

    // ---- init ----
    for (int i = tid; i < 4 * BT * HP; i += NTHR)
        ((float*)S->h1s)[i] = 0.f;                 // zeros 4 h arrays incl pads
    if (tid < 200) {
        S->b1c[tid] = b_ih1[tid] + b_hh1[tid];
        S->b2c[tid] = b_ih2[tid] + b_hh2[tid];
    }
    if (tid < 52)  S->wfcs[tid] = (tid < H) ? w_fc[tid] : 0.f;
    if (tid == 0)  S->bfcs = b_fc[0];
    __syncthreads();
    if (tid < BT * IND) {                          // x(0) into h1 row slots
        int b = tid >> 2, d = tid & 3;
        S->h1s[b][H + d] = x[(B0 + b) * IND + d];
    }

    // ---- per-thread packed weights; uniform 28-pair rows ----
    // band 0 [0,200)   : w_hh1 row pairs 0..24, w_ih1 pairs 25..26, 27 = 0; h1s  -> g1p
    // band 1 [200,400) : w_ih2 row pairs 0..24, rest 0;                h1rs -> g2ap
    // band 2 [400,600) : w_hh2 row pairs 0..24, rest 0;                h2s  -> g2bp
    ull w2[NPAIR];
#pragma unroll
    for (int q = 0; q < NPAIR; q++) w2[q] = 0ULL;
    const ull* hb = (const ull*)S->h1s;
    ull*       gd = S->g1p;

    if (tid < 600) {
        const int band = (tid >= 400) ? 2 : (tid >= 200 ? 1 : 0);
        const int g    = tid - band * 200;
        const float* wsrc = (band == 0) ? w_hh1 : (band == 1) ? w_ih2 : w_hh2;
#pragma unroll
        for (int q = 0; q < 25; q++)
            w2[q] = pack2(wsrc[g * H + 2 * q], wsrc[g * H + 2 * q + 1]);
        if (band == 0) {
            w2[25] = pack2(w_ih1[g * IND + 0], w_ih1[g * IND + 1]);
            w2[26] = pack2(w_ih1[g * IND + 2], w_ih1[g * IND + 3]);
            hb = (const ull*)S->h1s;  gd = S->g1p  + g * BT;
        } else if (band == 1) {
            hb = (const ull*)S->h1rs; gd = S->g2ap + g * BT;
        } else {
            hb = (const ull*)S->h2s;  gd = S->g2bp + g * BT;
        }
    }

    float cst0 = 0.f, cst1 = 0.f, cst2 = 0.f;
    __syncthreads();

    // Pipeline: A(t): L1-gates(t) || L2-gates(t-1) || FC(t-2) || prefetch x(t+1)
    //           B(t): L1-update(t) || L2-update(t-1) || copy x(t+1) into h1 slots
    for (int t = 0; t <= SEQ + 1; ++t) {
        // ================= phase A =================
        if (tid < 600) {
            const bool l1band = (tid < 200);
            const bool act = l1band ? (t < SEQ) : (t >= 1 && t <= SEQ);
            if (act) {
#pragma unroll 2
                for (int b = 0; b < BT; b++) {
                    const ulonglong2* hp = (const ulonglong2*)(hb + b * NPAIR);
                    ull a0 = 0ULL, a1 = 0ULL;
#pragma unroll
                    for (int q = 0; q < 14; q++) {
                        ulonglong2 hv = hp[q];          // LDS.128 broadcast
                        fma2(a0, w2[2 * q],     hv.x);
                        fma2(a1, w2[2 * q + 1], hv.y);
                    }
                    gd[b] = add2(a0, a1);               // STS.64 pair-sum
                }
            }
        } else if (tid < 616) {
            if (t >= 2) {                               // FC for step t-2
                const int b = tid - 600;
                float a0 = S->bfcs, a1 = 0.f, a2 = 0.f, a3 = 0.f;
#pragma unroll
                for (int q = 0; q < 13; q++) {
                    float4 wv = *(const float4*)&S->wfcs[4 * q];
                    float4 hv = *(const float4*)&S->h2rs[b][4 * q];
                    a0 += wv.x * hv.x; a1 += wv.y * hv.y;
                    a2 += wv.z * hv.z; a3 += wv.w * hv.w;
                }
                out[(t - 2) * BATCH + B0 + b] = (a0 + a1) + (a2 + a3);
            }
        } else if (tid < 624) {
            if (t + 1 < SEQ) {                          // prefetch x(t+1) -> xs
                const int i = tid - 616;                // 0..7
#pragma unroll
                for (int j = 0; j < 8; j++) {
                    int idx = i * 8 + j;
                    int b = idx >> 2, d = idx & 3;
                    S->xs[b][d] = x[((t + 1) * BATCH + B0 + b) * IND + d];
                }
            }
        }
        __syncthreads();

        // ================= phase B =================
        // cells 0..799 = L1(t), 800..1599 = L2(t-1); warp-aligned role splits
        {   // j = 0 : cells 0..639 (all L1)
            if (t < SEQ) l1_update(S, tid >> 4, tid & 15, cst0);
        }
        {   // j = 1 : tid<160 -> L1 cells 640..799 ; tid>=160 -> L2 r 0..479
            if (tid < 160) {
                if (t < SEQ) { int r = 640 + tid; l1_update(S, r >> 4, r & 15, cst1); }
            } else {
                if (t >= 1 && t <= SEQ) { int r = tid - 160; l2_update(S, r >> 4, r & 15, cst1); }
            }
        }
        {   // j = 2 : tid<320 -> L2 r 480..799 ; tid in [320,384) -> x copy
            if (tid < 320) {
                if (t >= 1 && t <= SEQ) { int r = 480 + tid; l2_update(S, r >> 4, r & 15, cst2); }
            } else if (tid < 384) {
                if (t + 1 < SEQ) {
                    int i2 = tid - 320;                 // 0..63
                    int b = i2 >> 2, d = i2 & 3;
                    S->h1s[b][H + d] = S->xs[b][d];     // x(t+1) into h1 row slots
                }
            }
        }
        __syncthreads();
    }
}

extern "C" void kernel_launch(void* const* d_in, const int* in_sizes, int n_in,
                              void* d_out, int out_size)
{
    const float* x     = (const float*)d_in[0];
    const float* w_ih1 = (const float*)d_in[1];
    const float* w_hh1 = (const float*)d_in[2];
    const float* b_ih1 = (const float*)d_in[3];
    const float* b_hh1 = (const float*)d_in[4];
    const float* w_ih2 = (const float*)d_in[5];
    const float* w_hh2 = (const float*)d_in[6];
    const float* b_ih2 = (const float*)d_in[7];
    const float* b_hh2 = (const float*)d_in[8];
    const float* w_fc  = (const float*)d_in[9];
    const float* b_fc  = (const float*)d_in[10];
    float* out = (float*)d_out;

    cudaFuncSetAttribute(lstm_fused_kernel,
                         cudaFuncAttributeMaxDynamicSharedMemorySize,
                         (int)sizeof(Smem));
    lstm_fused_kernel<<<NCTA, NTHR, sizeof(Smem)>>>(
        x, w_ih1, w_hh1, b_ih1, b_hh1,
        w_ih2, w_hh2, b_ih2, b_hh2, w_fc, b_fc, out);
}

// round 7
// speedup vs baseline: 1.7149x; 1.7149x over previous
#include <cuda_runtime.h>

#define SEQ   512
#define BATCH 2048
#define IND   4
#define H     50
#define BT    16                 // batch tile per CTA
#define NCTA  (BATCH / BT)       // 128
#define NTHR  640                // 20 warps, 5 per SMSP exactly
#define HP    56                 // floats per h row: 50 h + 4 x + 2 pad = 28 pairs
#define NPAIR 28
#define GS    17                 // gate-row stride in ull: 17 coprime w/ 16 bank-pairs
                                 // -> conflict-free STS.64/LDS.64 (round-6 bug was GS=16)

typedef unsigned long long ull;

// ---- packed dual-fp32 (sm_103a FFMA2 path, PTX-only) ----
__device__ __forceinline__ ull pack2(float lo, float hi) {
    ull r; asm("mov.b64 %0, {%1, %2};" : "=l"(r) : "f"(lo), "f"(hi)); return r;
}
__device__ __forceinline__ void unpack2(ull v, float& lo, float& hi) {
    asm("mov.b64 {%0, %1}, %2;" : "=f"(lo), "=f"(hi) : "l"(v));
}
__device__ __forceinline__ void fma2(ull& d, ull a, ull b) {
    asm("fma.rn.f32x2 %0, %1, %2, %0;" : "+l"(d) : "l"(a), "l"(b));
}
__device__ __forceinline__ ull add2(ull a, ull b) {
    ull r; asm("add.rn.f32x2 %0, %1, %2;" : "=l"(r) : "l"(a), "l"(b)); return r;
}

// ---- fast activations (known-good: final rel_err ~1.5e-7) ----
__device__ __forceinline__ float sigf(float x) {
    return __fdividef(1.0f, 1.0f + __expf(-x));
}
__device__ __forceinline__ float tanh_fast(float x) {
    float ax = fabsf(x);
    float e  = __expf(-2.0f * ax);
    float t  = __fdividef(1.0f - e, 1.0f + e);
    return copysignf(t, x);
}

struct Smem {
    float h1s [BT][HP];      // layer1 h (+ x in slots 50..53, zeros 54..55)
    float h1rs[BT][HP];      // relu(h1)  (slots 50..55 stay zero)
    float h2s [BT][HP];      // layer2 h
    float h2rs[BT][HP];      // relu(h2)
    ull   g1p [200 * GS];    // L1 gate pair-sums   (stride 17: conflict-free)
    ull   g2ap[200 * GS];    // L2 w_ih2 part
    ull   g2bp[200 * GS];    // L2 w_hh2 part
    float b1c[200];          // b_ih1 + b_hh1
    float b2c[200];          // b_ih2 + b_hh2
    float xs[BT][IND];       // staged x(t+1)
    float wfcs[52];
    float bfcs;
};

__device__ __forceinline__ float hsum2(ull v, float bias) {
    float lo, hi; unpack2(v, lo, hi);
    return (lo + hi) + bias;
}

__device__ __forceinline__ void l1_update(Smem* S, int u, int b, float& c) {
    float gi = hsum2(S->g1p[(      u) * GS + b], S->b1c[u]);
    float gf = hsum2(S->g1p[(H   + u) * GS + b], S->b1c[H + u]);
    float gg = hsum2(S->g1p[(2*H + u) * GS + b], S->b1c[2*H + u]);
    float go = hsum2(S->g1p[(3*H + u) * GS + b], S->b1c[3*H + u]);
    float cn = sigf(gf) * c + sigf(gi) * tanh_fast(gg);
    c = cn;
    float hv = sigf(go) * tanh_fast(cn);
    S->h1s[b][u]  = hv;
    S->h1rs[b][u] = fmaxf(hv, 0.f);
}

__device__ __forceinline__ void l2_update(Smem* S, int u, int b, float& c) {
    float gi = hsum2(add2(S->g2ap[(      u) * GS + b], S->g2bp[(      u) * GS + b]), S->b2c[u]);
    float gf = hsum2(add2(S->g2ap[(H   + u) * GS + b], S->g2bp[(H   + u) * GS + b]), S->b2c[H + u]);
    float gg = hsum2(add2(S->g2ap[(2*H + u) * GS + b], S->g2bp[(2*H + u) * GS + b]), S->b2c[2*H + u]);
    float go = hsum2(add2(S->g2ap[(3*H + u) * GS + b], S->g2bp[(3*H + u) * GS + b]), S->b2c[3*H + u]);
    float cn = sigf(gf) * c + sigf(gi) * tanh_fast(gg);
    c = cn;
    float hv = sigf(go) * tanh_fast(cn);
    S->h2s[b][u]  = hv;
    S->h2rs[b][u] = fmaxf(hv, 0.f);
}

__global__ __launch_bounds__(NTHR, 1)
void lstm_fused_kernel(
    const float* __restrict__ x,
    const float* __restrict__ w_ih1, const float* __restrict__ w_hh1,
    const float* __restrict__ b_ih1, const float* __restrict__ b_hh1,
    const float* __restrict__ w_ih2, const float* __restrict__ w_hh2,
    const float* __restrict__ b_ih2, const float* __restrict__ b_hh2,
    const float* __restrict__ w_fc,  const float* __restrict__ b_fc,
    float* __restrict__ out)
{
    extern __shared__ char smem_raw[];
    Smem* S = (Smem*)smem_raw;

    const int tid = threadIdx.x;
    const int B0  = blockIdx.x * BT;

    // ---- init ----
    for (int i = tid; i < 4 * BT * HP; i += NTHR)
        ((float*)S->h1s)[i] = 0.f;                 // zeros 4 h arrays incl pads
    if (tid < 200) {
        S->b1c[tid] = b_ih1[tid] + b_hh1[tid];
        S->b2c[tid] = b_ih2[tid] + b_hh2[tid];
    }
    if (tid < 52)  S->wfcs[tid] = (tid < H) ? w_fc[tid] : 0.f;
    if (tid == 0)  S->bfcs = b_fc[0];
    __syncthreads();
    if (tid < BT * IND) {                          // x(0) into h1 row slots
        int b = tid >> 2, d = tid & 3;
        S->h1s[b][H + d] = x[(B0 + b) * IND + d];
    }

    // ---- per-thread packed weights; uniform 28-pair rows ----
    // band 0 [0,200)   : w_hh1 pairs 0..24, w_ih1 pairs 25..26, pair 27 = 0; h1s  -> g1p
    // band 1 [200,400) : w_ih2 pairs 0..24, rest 0;                          h1rs -> g2ap
    // band 2 [400,600) : w_hh2 pairs 0..24, rest 0;                          h2s  -> g2bp
    ull w2[NPAIR];
#pragma unroll
    for (int q = 0; q < NPAIR; q++) w2[q] = 0ULL;
    const ull* hb = (const ull*)S->h1s;
    ull*       gd = S->g1p;

    if (tid < 600) {
        const int band = (tid >= 400) ? 2 : (tid >= 200 ? 1 : 0);
        const int g    = tid - band * 200;
        const float* wsrc = (band == 0) ? w_hh1 : (band == 1) ? w_ih2 : w_hh2;
#pragma unroll
        for (int q = 0; q < 25; q++)
            w2[q] = pack2(wsrc[g * H + 2 * q], wsrc[g * H + 2 * q + 1]);
        if (band == 0) {
            w2[25] = pack2(w_ih1[g * IND + 0], w_ih1[g * IND + 1]);
            w2[26] = pack2(w_ih1[g * IND + 2], w_ih1[g * IND + 3]);
            hb = (const ull*)S->h1s;  gd = S->g1p  + g * GS;
        } else if (band == 1) {
            hb = (const ull*)S->h1rs; gd = S->g2ap + g * GS;
        } else {
            hb = (const ull*)S->h2s;  gd = S->g2bp + g * GS;
        }
    }

    float cst0 = 0.f, cst1 = 0.f, cst2 = 0.f;
    __syncthreads();

    // Pipeline: A(t): L1-gates(t) || L2-gates(t-1) || FC(t-2) || prefetch x(t+1)
    //           B(t): L1-update(t) || L2-update(t-1) || copy x(t+1) into h1 slots
    for (int t = 0; t <= SEQ + 1; ++t) {
        // ================= phase A =================
        if (tid < 600) {
            const bool l1band = (tid < 200);
            const bool act = l1band ? (t < SEQ) : (t >= 1 && t <= SEQ);
            if (act) {
#pragma unroll 2
                for (int b = 0; b < BT; b++) {
                    const ulonglong2* hp = (const ulonglong2*)(hb + b * NPAIR);
                    ull a0 = 0ULL, a1 = 0ULL;
#pragma unroll
                    for (int q = 0; q < 14; q++) {
                        ulonglong2 hv = hp[q];          // LDS.128 broadcast
                        fma2(a0, w2[2 * q],     hv.x);
                        fma2(a1, w2[2 * q + 1], hv.y);
                    }
                    gd[b] = add2(a0, a1);               // STS.64, conflict-free (GS=17)
                }
            }
        } else if (tid < 616) {
            if (t >= 2) {                               // FC for step t-2
                const int b = tid - 600;
                float a0 = S->bfcs, a1 = 0.f, a2 = 0.f, a3 = 0.f;
#pragma unroll
                for (int q = 0; q < 13; q++) {
                    float4 wv = *(const float4*)&S->wfcs[4 * q];
                    float4 hv = *(const float4*)&S->h2rs[b][4 * q];
                    a0 += wv.x * hv.x; a1 += wv.y * hv.y;
                    a2 += wv.z * hv.z; a3 += wv.w * hv.w;
                }
                out[(t - 2) * BATCH + B0 + b] = (a0 + a1) + (a2 + a3);
            }
        } else if (tid < 624) {
            if (t + 1 < SEQ) {                          // prefetch x(t+1) -> xs
                const int i = tid - 616;                // 0..7
#pragma unroll
                for (int j = 0; j < 8; j++) {
                    int idx = i * 8 + j;
                    int b = idx >> 2, d = idx & 3;
                    S->xs[b][d] = x[((t + 1) * BATCH + B0 + b) * IND + d];
                }
            }
        }
        __syncthreads();

        // ================= phase B =================
        // cells 0..799 = L1(t), 800..1599 = L2(t-1); warp-aligned role splits
        {   // j = 0 : cells 0..639 (all L1)
            if (t < SEQ) l1_update(S, tid >> 4, tid & 15, cst0);
        }
        {   // j = 1 : tid<160 -> L1 cells 640..799 ; tid>=160 -> L2 r 0..479
            if (tid < 160) {
                if (t < SEQ) { int r = 640 + tid; l1_update(S, r >> 4, r & 15, cst1); }
            } else {
                if (t >= 1 && t <= SEQ) { int r = tid - 160; l2_update(S, r >> 4, r & 15, cst1); }
            }
        }
        {   // j = 2 : tid<320 -> L2 r 480..799 ; tid in [320,384) -> x copy
            if (tid < 320) {
                if (t >= 1 && t <= SEQ) { int r = 480 + tid; l2_update(S, r >> 4, r & 15, cst2); }
            } else if (tid < 384) {
                if (t + 1 < SEQ) {
                    int i2 = tid - 320;                 // 0..63
                    int b = i2 >> 2, d = i2 & 3;
                    S->h1s[b][H + d] = S->xs[b][d];     // x(t+1) into h1 row slots
                }
            }
        }
        __syncthreads();
    }
}

extern "C" void kernel_launch(void* const* d_in, const int* in_sizes, int n_in,
                              void* d_out, int out_size)
{
    const float* x     = (const float*)d_in[0];
    const float* w_ih1 = (const float*)d_in[1];
    const float* w_hh1 = (const float*)d_in[2];
    const float* b_ih1 = (const float*)d_in[3];
    const float* b_hh1 = (const float*)d_in[4];
    const float* w_ih2 = (const float*)d_in[5];
    const float* w_hh2 = (const float*)d_in[6];
    const float* b_ih2 = (const float*)d_in[7];
    const float* b_hh2 = (const float*)d_in[8];
    const float* w_fc  = (const float*)d_in[9];
    const float* b_fc  = (const float*)d_in[10];
    float* out = (float*)d_out;

    cudaFuncSetAttribute(lstm_fused_kernel,
                         cudaFuncAttributeMaxDynamicSharedMemorySize,
                         (int)sizeof(Smem));
    lstm_fused_kernel<<<NCTA, NTHR, sizeof(Smem)>>>(
        x, w_ih1, w_hh1, b_ih1, b_hh1,
        w_ih2, w_hh2, b_ih2, b_hh2, w_fc, b_fc, out);
}